// round 16
// baseline (speedup 1.0000x reference)
#include <cuda_runtime.h>
#include <cuda_bf16.h>
#include <math.h>
#include <stdint.h>
#include <cstdint>
#include <cstddef>

// Problem constants
#define S_TOK 8192
#define C_DIM 1024
#define H_DIM 4096
#define NEXP  8
#define CAP   2560

// GEMM tiling: 128(M) x 128(N) x 32(K), 256 threads, warps 2(M) x 4(N), warp tile 64x32
#define BM 128
#define BN 128
#define BK 32
// 3-stage pipeline: stage = A(16KB) + B(16KB) = 32KB
#define STAGE_BYTES 32768
#define B_OFF_BYTES 16384
#define SMEM_GEMM_BYTES (3 * STAGE_BYTES)   // 98304

// ---------------- device scratch (statics ~369 MB, proven envelope) ----------------
__device__ int                g_cand_count[NEXP];
__device__ int                g_cand_tok[NEXP * S_TOK];
__device__ unsigned long long g_cand_key[NEXP * S_TOK];
__device__ float              g_cand_gate[NEXP * S_TOK];
__device__ int                g_tb[NEXP * CAP];
__device__ float              g_gb[NEXP * CAP];
__device__ float              g_probs_sum[NEXP];

__device__ float g_xt[S_TOK * C_DIM];                    // tf32-rounded x (32 MiB)
__device__ float g_h[(size_t)NEXP * CAP * H_DIM];        // tf32-rounded h (320 MiB)

// ---------------- helpers ----------------
__device__ __forceinline__ unsigned int to_tf32_u(float v) {
    unsigned int u;
    asm("cvt.rna.tf32.f32 %0, %1;\n" : "=r"(u) : "f"(v));
    return u;
}
__device__ __forceinline__ float to_tf32_f(float v) {
    return __uint_as_float(to_tf32_u(v));
}
__device__ __forceinline__ void cpa16(unsigned int saddr, const void* g) {
    asm volatile("cp.async.cg.shared.global [%0], [%1], 16;\n" :: "r"(saddr), "l"(g));
}
__device__ __forceinline__ void cpa_commit() {
    asm volatile("cp.async.commit_group;\n" ::: "memory");
}
__device__ __forceinline__ void cpa_wait1() {
    asm volatile("cp.async.wait_group 1;\n" ::: "memory");
}
__device__ __forceinline__ void cpa_wait0() {
    asm volatile("cp.async.wait_group 0;\n" ::: "memory");
}
__device__ __forceinline__ void mma_tf32(float* c, const unsigned int* a, const unsigned int* b) {
    asm volatile("mma.sync.aligned.m16n8k8.row.col.f32.tf32.tf32.f32 "
                 "{%0,%1,%2,%3}, {%4,%5,%6,%7}, {%8,%9}, {%0,%1,%2,%3};\n"
                 : "+f"(c[0]), "+f"(c[1]), "+f"(c[2]), "+f"(c[3])
                 : "r"(a[0]), "r"(a[1]), "r"(a[2]), "r"(a[3]), "r"(b[0]), "r"(b[1]));
}
__device__ __forceinline__ float gelu_exact(float v) {
    return 0.5f * v * (1.0f + erff(v * 0.70710678118654752440f));
}

// ---------------- init ----------------
__global__ void init_kernel() {
    int i = blockIdx.x * blockDim.x + threadIdx.x;
    if (i < NEXP) { g_cand_count[i] = 0; g_probs_sum[i] = 0.f; }
    if (i < NEXP * CAP) { g_tb[i] = 0; g_gb[i] = 0.f; }
}

// ---------------- router (exact fp32; also emits tf32-rounded x) ----------------
__global__ void __launch_bounds__(256) router_kernel(const float* __restrict__ x,
                              const float* __restrict__ rw,
                              const float* __restrict__ rb) {
    __shared__ float wsh[NEXP * C_DIM];
    __shared__ float psum[NEXP];
    int tid = threadIdx.x;
    for (int i = tid; i < NEXP * C_DIM; i += 256) {
        int e = i / C_DIM, c = i % C_DIM;
        wsh[i] = rw[c * NEXP + e];
    }
    if (tid < NEXP) psum[tid] = 0.f;
    __syncthreads();

    int warp = tid >> 5, lane = tid & 31;
    int s = blockIdx.x * 8 + warp;

    float acc[NEXP];
#pragma unroll
    for (int e = 0; e < NEXP; e++) acc[e] = 0.f;
    const float* xp = x + (size_t)s * C_DIM;
    float* xtp = g_xt + (size_t)s * C_DIM;
    for (int c = lane; c < C_DIM; c += 32) {
        float xv = xp[c];
        xtp[c] = to_tf32_f(xv);               // fused convert_x
#pragma unroll
        for (int e = 0; e < NEXP; e++) acc[e] += xv * wsh[e * C_DIM + c];
    }
#pragma unroll
    for (int e = 0; e < NEXP; e++) {
#pragma unroll
        for (int off = 16; off > 0; off >>= 1)
            acc[e] += __shfl_down_sync(0xffffffffu, acc[e], off);
    }
    if (lane == 0) {
        float lg[NEXP];
        float mx = -1e30f;
#pragma unroll
        for (int e = 0; e < NEXP; e++) { lg[e] = acc[e] + rb[e]; mx = fmaxf(mx, lg[e]); }
        float sum = 0.f;
#pragma unroll
        for (int e = 0; e < NEXP; e++) { lg[e] = expf(lg[e] - mx); sum += lg[e]; }
        float inv = 1.f / sum;
        float p[NEXP];
#pragma unroll
        for (int e = 0; e < NEXP; e++) { p[e] = lg[e] * inv; atomicAdd(&psum[e], p[e]); }
        int i1 = 0; float v1 = p[0];
#pragma unroll
        for (int e = 1; e < NEXP; e++) if (p[e] > v1) { v1 = p[e]; i1 = e; }
        int i2 = -1; float v2 = -1.f;
#pragma unroll
        for (int e = 0; e < NEXP; e++) if (e != i1 && p[e] > v2) { v2 = p[e]; i2 = e; }

        int pos1 = atomicAdd(&g_cand_count[i1], 1);
        g_cand_tok[i1 * S_TOK + pos1] = s;
        g_cand_gate[i1 * S_TOK + pos1] = v1;
        g_cand_key[i1 * S_TOK + pos1] =
            ((unsigned long long)(0xFFFFFFFFu - __float_as_uint(v1)) << 32) | (unsigned int)s;
        int pos2 = atomicAdd(&g_cand_count[i2], 1);
        g_cand_tok[i2 * S_TOK + pos2] = s;
        g_cand_gate[i2 * S_TOK + pos2] = v2;
        g_cand_key[i2 * S_TOK + pos2] =
            ((unsigned long long)(0xFFFFFFFFu - __float_as_uint(v2)) << 32) | (unsigned int)s;
    }
    __syncthreads();
    if (tid < NEXP) atomicAdd(&g_probs_sum[tid], psum[tid]);
}

// ---------------- rank (counting rank on unique keys) ----------------
__global__ void __launch_bounds__(256) rank_kernel() {
    int e = blockIdx.y;
    int n = g_cand_count[e];
    int i = blockIdx.x * 256 + threadIdx.x;
    unsigned long long mykey = (i < n) ? g_cand_key[e * S_TOK + i] : ~0ULL;
    int rank = 0;
    __shared__ unsigned long long sk[256];
    for (int t0 = 0; t0 < n; t0 += 256) {
        int j = t0 + threadIdx.x;
        sk[threadIdx.x] = (j < n) ? g_cand_key[e * S_TOK + j] : ~0ULL;
        __syncthreads();
        int lim = min(256, n - t0);
        for (int j2 = 0; j2 < lim; j2++) rank += (sk[j2] < mykey) ? 1 : 0;
        __syncthreads();
    }
    if (i < n && rank < CAP) {
        g_tb[e * CAP + rank] = g_cand_tok[e * S_TOK + i];
        g_gb[e * CAP + rank] = g_cand_gate[e * S_TOK + i];
    }
}

// ---------------- TF32 MMA GEMM body (128x128x32, warp tile 64x32, 3-stage) ----------------
// Logical-k permutation (same for A and B, dot-product invariant):
//   logical slot s<4 -> physical 2s ; s>=4 -> physical 2(s-4)+1
// A smem: [128 m][16 pairs of 2 words]; pair p stored at slot (p + 4*(m&3)) & 15
//         -> fragment = ld.shared.v2.b32 (words for logical l3 and l3+4 adjacent)
// B smem: [32 k][128 n words], word swizzle: n' = (n + 8*((k>>1)&3)) & 127
// MODE 1: h = gelu(gather(x_t) @ w1 + b1); B = w1[e] [C][H] (k-major rows)
// MODE 2: y += gate * (h @ w2 + b2);       B = w2[e] [H][C]
template <int MODE>
__device__ __forceinline__ void moe_gemm_body(float* smf,
                                              const float* __restrict__ w,
                                              const float* __restrict__ bias,
                                              float* __restrict__ y) {
    unsigned int sbase = (unsigned int)__cvta_generic_to_shared(smf);

    int e = blockIdx.z;
    int n_e = min(g_cand_count[e], CAP);
    int row0 = blockIdx.x * BM;
    if (row0 >= n_e) return;
    int col0 = blockIdx.y * BN;

    int tid = threadIdx.x, lane = tid & 31, wid = tid >> 5;
    int wm = wid >> 2, wn = wid & 3;   // warp tile 64(M) x 32(N)

    const int K   = (MODE == 1) ? C_DIM : H_DIM;
    const int LDB = (MODE == 1) ? H_DIM : C_DIM;
    const int NK  = K / BK;

    // ---- A fill: thread t -> rows t>>3 (+32,+64,+96), chunk t&7 (16B = 2 pairs)
    int aRow = tid >> 3;      // 0..31
    int aC   = tid & 7;
    const float* aSrc[4];
    unsigned int aDst[4];
#pragma unroll
    for (int i = 0; i < 4; i++) {
        int r = aRow + 32 * i;
        if (MODE == 1) {
            aSrc[i] = g_xt + (size_t)g_tb[e * CAP + row0 + r] * C_DIM;
        } else {
            aSrc[i] = g_h + ((size_t)e * CAP + row0 + r) * H_DIM;
        }
        aDst[i] = (unsigned int)(r * 128 + (((aC + 2 * (r & 3)) & 7) << 4));
    }

    // ---- B fill: thread t -> row t>>3 (0..31), chunks (t&7)+8i, i=0..3
    int bRow = tid >> 3;      // 0..31 (k)
    int bC   = tid & 7;
    const float* bSrcBase = w + (size_t)e * C_DIM * H_DIM;
    unsigned int bDst[4];
#pragma unroll
    for (int i = 0; i < 4; i++) {
        int c = bC + 8 * i;   // chunk 0..31 in the 128-word row
        bDst[i] = (unsigned int)(B_OFF_BYTES + bRow * 512 +
                                 (((4 * c + 8 * ((bRow >> 1) & 3)) & 127) << 2));
    }

    float acc[4][4][4];
#pragma unroll
    for (int a = 0; a < 4; a++)
#pragma unroll
        for (int b = 0; b < 4; b++)
#pragma unroll
            for (int c = 0; c < 4; c++) acc[a][b][c] = 0.f;

    // prologue: fill stages 0 and 1
#pragma unroll
    for (int p = 0; p < 2; p++) {
        unsigned int sb = sbase + p * STAGE_BYTES;
        int k0 = p * BK;
#pragma unroll
        for (int i = 0; i < 4; i++)
            cpa16(sb + aDst[i], aSrc[i] + k0 + aC * 4);
        const float* bRowK = bSrcBase + (size_t)(k0 + bRow) * LDB + col0;
#pragma unroll
        for (int i = 0; i < 4; i++)
            cpa16(sb + bDst[i], bRowK + (bC + 8 * i) * 4);
        cpa_commit();
    }

    int l4 = lane >> 2;      // 0..7
    int l3 = lane & 3;       // 0..3

    int stage = 0;
    for (int kc0 = 0; kc0 < NK; kc0++) {
        if (kc0 + 1 < NK) cpa_wait1(); else cpa_wait0();
        __syncthreads();

        // prefetch chunk kc0+2 into slot (stage+2)%3
        if (kc0 + 2 < NK) {
            int sn = stage + 2; if (sn >= 3) sn -= 3;
            unsigned int sb = sbase + sn * STAGE_BYTES;
            int k0 = (kc0 + 2) * BK;
#pragma unroll
            for (int i = 0; i < 4; i++)
                cpa16(sb + aDst[i], aSrc[i] + k0 + aC * 4);
            const float* bRowK = bSrcBase + (size_t)(k0 + bRow) * LDB + col0;
#pragma unroll
            for (int i = 0; i < 4; i++)
                cpa16(sb + bDst[i], bRowK + (bC + 8 * i) * 4);
            cpa_commit();
        }

        const float* As = smf + stage * (STAGE_BYTES / 4);
        const float* Bs = As + (B_OFF_BYTES / 4);

#pragma unroll
        for (int kk = 0; kk < BK; kk += 8) {
            // A fragments: one v2 load per (mt, row-half); pair slot shared across mt
            int slot = (((kk >> 1) + l3) + 4 * (l4 & 3)) & 15;
            unsigned int af[4][4];
#pragma unroll
            for (int mt = 0; mt < 4; mt++) {
                int rb = wm * 64 + mt * 16 + l4;
                float2 v0 = *(const float2*)(As + rb * 32 + 2 * slot);
                float2 v1 = *(const float2*)(As + (rb + 8) * 32 + 2 * slot);
                af[mt][0] = __float_as_uint(v0.x);   // logical l3   -> physical kk+2*l3
                af[mt][2] = __float_as_uint(v0.y);   // logical l3+4 -> physical kk+2*l3+1
                af[mt][1] = __float_as_uint(v1.x);
                af[mt][3] = __float_as_uint(v1.y);
            }
            // B fragments: rows kk+2*l3 and kk+2*l3+1 (same permutation)
            int krow0 = kk + 2 * l3;
            int boff = 8 * (((kk >> 1) + l3) & 3);
            unsigned int bf[4][2];
#pragma unroll
            for (int nt = 0; nt < 4; nt++) {
                int nb = wn * 32 + nt * 8 + l4;
                int cw = (nb + boff) & 127;
                bf[nt][0] = to_tf32_u(Bs[krow0 * 128 + cw]);
                bf[nt][1] = to_tf32_u(Bs[(krow0 + 1) * 128 + cw]);
            }
#pragma unroll
            for (int mt = 0; mt < 4; mt++)
#pragma unroll
                for (int nt = 0; nt < 4; nt++)
                    mma_tf32(acc[mt][nt], af[mt], bf[nt]);
        }

        stage++; if (stage == 3) stage = 0;
    }

    // ---------------- epilogue ----------------
    const float* brw = bias + (MODE == 1 ? e * H_DIM : e * C_DIM);
#pragma unroll
    for (int mt = 0; mt < 4; mt++) {
#pragma unroll
        for (int half = 0; half < 2; half++) {
            int r = row0 + wm * 64 + mt * 16 + l4 + half * 8;
#pragma unroll
            for (int nt = 0; nt < 4; nt++) {
                int n0 = col0 + wn * 32 + nt * 8 + l3 * 2;
                float c0 = acc[mt][nt][half * 2 + 0];
                float c1 = acc[mt][nt][half * 2 + 1];
                if (MODE == 1) {
                    float v0 = to_tf32_f(gelu_exact(c0 + brw[n0]));
                    float v1 = to_tf32_f(gelu_exact(c1 + brw[n0 + 1]));
                    float2* hp = (float2*)(g_h + ((size_t)e * CAP + r) * H_DIM + n0);
                    *hp = make_float2(v0, v1);
                } else {
                    float gate = g_gb[e * CAP + r];
                    if (gate != 0.f) {
                        int tok = g_tb[e * CAP + r];
                        float* yrow = y + (size_t)tok * C_DIM + n0;
                        atomicAdd(&yrow[0], (c0 + brw[n0]) * gate);
                        atomicAdd(&yrow[1], (c1 + brw[n0 + 1]) * gate);
                    }
                }
            }
        }
    }
}

// concrete kernels: cap regs at 128 (2 blocks/SM)
__global__ void __launch_bounds__(256, 2) moe_gemm1(const float* __restrict__ w1,
                                                    const float* __restrict__ b1) {
    extern __shared__ float smf_g1[];
    moe_gemm_body<1>(smf_g1, w1, b1, (float*)0);
}
__global__ void __launch_bounds__(256, 2) moe_gemm2(const float* __restrict__ w2,
                                                    const float* __restrict__ b2,
                                                    float* __restrict__ y) {
    extern __shared__ float smf_g2[];
    moe_gemm_body<2>(smf_g2, w2, b2, y);
}

// ---------------- aux loss ----------------
__global__ void aux_kernel(float* __restrict__ out, int out_size) {
    if (out_size <= S_TOK * C_DIM) return;
    float total = 0.f;
    float kept[NEXP];
    for (int e = 0; e < NEXP; e++) {
        kept[e] = (float)min(g_cand_count[e], CAP);
        total += kept[e];
    }
    float aux = 0.f;
    for (int e = 0; e < NEXP; e++) {
        float pm = g_probs_sum[e] / (float)S_TOK;
        aux += pm * (kept[e] / (total + 1e-9f));
    }
    out[S_TOK * C_DIM] = aux * (float)NEXP;
}

// ---------------- launch ----------------
extern "C" void kernel_launch(void* const* d_in, const int* in_sizes, int n_in,
                              void* d_out, int out_size) {
    const float* x  = (const float*)d_in[0];
    const float* rw = (const float*)d_in[1];
    const float* rb = (const float*)d_in[2];
    const float* w1 = (const float*)d_in[3];
    const float* b1 = (const float*)d_in[4];
    const float* w2 = (const float*)d_in[5];
    const float* b2 = (const float*)d_in[6];
    float* out = (float*)d_out;

    cudaFuncSetAttribute((const void*)moe_gemm1,
                         cudaFuncAttributeMaxDynamicSharedMemorySize, SMEM_GEMM_BYTES);
    cudaFuncSetAttribute((const void*)moe_gemm2,
                         cudaFuncAttributeMaxDynamicSharedMemorySize, SMEM_GEMM_BYTES);

    init_kernel<<<(NEXP * CAP + 255) / 256, 256>>>();
    cudaMemsetAsync(d_out, 0, (size_t)out_size * sizeof(float));

    router_kernel<<<S_TOK / 8, 256>>>(x, rw, rb);   // also fills g_xt
    rank_kernel<<<dim3(S_TOK / 256, NEXP), 256>>>();

    moe_gemm1<<<dim3(CAP / BM, H_DIM / BN, NEXP), 256, SMEM_GEMM_BYTES>>>(w1, b1);
    moe_gemm2<<<dim3(CAP / BM, C_DIM / BN, NEXP), 256, SMEM_GEMM_BYTES>>>(w2, b2, out);

    aux_kernel<<<1, 1>>>(out, out_size);
}

// round 17
// speedup vs baseline: 1.0600x; 1.0600x over previous
#include <cuda_runtime.h>
#include <cuda_bf16.h>
#include <math.h>
#include <stdint.h>
#include <cstdint>
#include <cstddef>

// Problem constants
#define S_TOK 8192
#define C_DIM 1024
#define H_DIM 4096
#define NEXP  8
#define CAP   2560

// GEMM tiling: 128(M) x 128(N) x 32(K), 256 threads, warps 2(M) x 4(N), warp tile 64x32
#define BM 128
#define BN 128
#define BK 32
#define KSPLIT2 2                         // split-K factor for GEMM2
#define KHALF (H_DIM / KSPLIT2)           // 2048
// smem float-index offsets (2 stages): A stage 128*32=4096 floats, B stage 32*128=4096 floats
#define FA0 0
#define FA1 4096
#define FB0 8192
#define FB1 12288
#define SMEM_GEMM_BYTES 65536

// ---------------- device scratch (statics ~369 MB, proven envelope) ----------------
__device__ int                g_cand_count[NEXP];
__device__ int                g_cand_tok[NEXP * S_TOK];
__device__ unsigned long long g_cand_key[NEXP * S_TOK];
__device__ float              g_cand_gate[NEXP * S_TOK];
__device__ int                g_tb[NEXP * CAP];
__device__ float              g_gb[NEXP * CAP];
__device__ float              g_probs_sum[NEXP];

__device__ float g_xt[S_TOK * C_DIM];                    // tf32-rounded x (32 MiB)
__device__ float g_h[(size_t)NEXP * CAP * H_DIM];        // tf32-rounded h (320 MiB)

// ---------------- helpers ----------------
__device__ __forceinline__ unsigned int to_tf32_u(float v) {
    unsigned int u;
    asm("cvt.rna.tf32.f32 %0, %1;\n" : "=r"(u) : "f"(v));
    return u;
}
__device__ __forceinline__ float to_tf32_f(float v) {
    return __uint_as_float(to_tf32_u(v));
}
__device__ __forceinline__ void cpa16(unsigned int saddr, const void* g) {
    asm volatile("cp.async.cg.shared.global [%0], [%1], 16;\n" :: "r"(saddr), "l"(g));
}
__device__ __forceinline__ void cpa_commit() {
    asm volatile("cp.async.commit_group;\n" ::: "memory");
}
__device__ __forceinline__ void cpa_wait1() {
    asm volatile("cp.async.wait_group 1;\n" ::: "memory");
}
__device__ __forceinline__ void cpa_wait0() {
    asm volatile("cp.async.wait_group 0;\n" ::: "memory");
}
__device__ __forceinline__ void mma_tf32(float* c, const unsigned int* a, const unsigned int* b) {
    asm volatile("mma.sync.aligned.m16n8k8.row.col.f32.tf32.tf32.f32 "
                 "{%0,%1,%2,%3}, {%4,%5,%6,%7}, {%8,%9}, {%0,%1,%2,%3};\n"
                 : "+f"(c[0]), "+f"(c[1]), "+f"(c[2]), "+f"(c[3])
                 : "r"(a[0]), "r"(a[1]), "r"(a[2]), "r"(a[3]), "r"(b[0]), "r"(b[1]));
}
__device__ __forceinline__ float gelu_exact(float v) {
    return 0.5f * v * (1.0f + erff(v * 0.70710678118654752440f));
}

// ---------------- init ----------------
__global__ void init_kernel() {
    int i = blockIdx.x * blockDim.x + threadIdx.x;
    if (i < NEXP) { g_cand_count[i] = 0; g_probs_sum[i] = 0.f; }
    if (i < NEXP * CAP) { g_tb[i] = 0; g_gb[i] = 0.f; }
}

// ---------------- x -> tf32-rounded copy ----------------
__global__ void __launch_bounds__(256) convert_x_kernel(const float* __restrict__ x) {
    int i = blockIdx.x * 256 + threadIdx.x;
    if (i < S_TOK * C_DIM) g_xt[i] = to_tf32_f(x[i]);
}

// ---------------- router (exact fp32) ----------------
__global__ void __launch_bounds__(256) router_kernel(const float* __restrict__ x,
                              const float* __restrict__ rw,
                              const float* __restrict__ rb) {
    __shared__ float wsh[NEXP * C_DIM];
    __shared__ float psum[NEXP];
    int tid = threadIdx.x;
    for (int i = tid; i < NEXP * C_DIM; i += 256) {
        int e = i / C_DIM, c = i % C_DIM;
        wsh[i] = rw[c * NEXP + e];
    }
    if (tid < NEXP) psum[tid] = 0.f;
    __syncthreads();

    int warp = tid >> 5, lane = tid & 31;
    int s = blockIdx.x * 8 + warp;

    float acc[NEXP];
#pragma unroll
    for (int e = 0; e < NEXP; e++) acc[e] = 0.f;
    const float* xp = x + (size_t)s * C_DIM;
    for (int c = lane; c < C_DIM; c += 32) {
        float xv = xp[c];
#pragma unroll
        for (int e = 0; e < NEXP; e++) acc[e] += xv * wsh[e * C_DIM + c];
    }
#pragma unroll
    for (int e = 0; e < NEXP; e++) {
#pragma unroll
        for (int off = 16; off > 0; off >>= 1)
            acc[e] += __shfl_down_sync(0xffffffffu, acc[e], off);
    }
    if (lane == 0) {
        float lg[NEXP];
        float mx = -1e30f;
#pragma unroll
        for (int e = 0; e < NEXP; e++) { lg[e] = acc[e] + rb[e]; mx = fmaxf(mx, lg[e]); }
        float sum = 0.f;
#pragma unroll
        for (int e = 0; e < NEXP; e++) { lg[e] = expf(lg[e] - mx); sum += lg[e]; }
        float inv = 1.f / sum;
        float p[NEXP];
#pragma unroll
        for (int e = 0; e < NEXP; e++) { p[e] = lg[e] * inv; atomicAdd(&psum[e], p[e]); }
        int i1 = 0; float v1 = p[0];
#pragma unroll
        for (int e = 1; e < NEXP; e++) if (p[e] > v1) { v1 = p[e]; i1 = e; }
        int i2 = -1; float v2 = -1.f;
#pragma unroll
        for (int e = 0; e < NEXP; e++) if (e != i1 && p[e] > v2) { v2 = p[e]; i2 = e; }

        int pos1 = atomicAdd(&g_cand_count[i1], 1);
        g_cand_tok[i1 * S_TOK + pos1] = s;
        g_cand_gate[i1 * S_TOK + pos1] = v1;
        g_cand_key[i1 * S_TOK + pos1] =
            ((unsigned long long)(0xFFFFFFFFu - __float_as_uint(v1)) << 32) | (unsigned int)s;
        int pos2 = atomicAdd(&g_cand_count[i2], 1);
        g_cand_tok[i2 * S_TOK + pos2] = s;
        g_cand_gate[i2 * S_TOK + pos2] = v2;
        g_cand_key[i2 * S_TOK + pos2] =
            ((unsigned long long)(0xFFFFFFFFu - __float_as_uint(v2)) << 32) | (unsigned int)s;
    }
    __syncthreads();
    if (tid < NEXP) atomicAdd(&g_probs_sum[tid], psum[tid]);
}

// ---------------- rank (counting rank on unique keys) ----------------
__global__ void __launch_bounds__(256) rank_kernel() {
    int e = blockIdx.y;
    int n = g_cand_count[e];
    int i = blockIdx.x * 256 + threadIdx.x;
    unsigned long long mykey = (i < n) ? g_cand_key[e * S_TOK + i] : ~0ULL;
    int rank = 0;
    __shared__ unsigned long long sk[256];
    for (int t0 = 0; t0 < n; t0 += 256) {
        int j = t0 + threadIdx.x;
        sk[threadIdx.x] = (j < n) ? g_cand_key[e * S_TOK + j] : ~0ULL;
        __syncthreads();
        int lim = min(256, n - t0);
        for (int j2 = 0; j2 < lim; j2++) rank += (sk[j2] < mykey) ? 1 : 0;
        __syncthreads();
    }
    if (i < n && rank < CAP) {
        g_tb[e * CAP + rank] = g_cand_tok[e * S_TOK + i];
        g_gb[e * CAP + rank] = g_cand_gate[e * S_TOK + i];
    }
}

// ---------------- TF32 MMA GEMM body (R14 mainloop; MODE2 adds split-K) ----------------
// A smem: [128 m][32 k words], chunk swizzle: chunk' = (chunk + (m&7)) & 7
// B smem: [32 k][128 n words], word swizzle:  n' = (n + 8*(k&3)) & 127
// MODE 1: h = gelu(gather(x_t) @ w1 + b1); B = w1[e] [C][H] (k-major rows)
// MODE 2: y += gate * (h @ w2 + b2); split-K=2 over H; bias added by split 0 only
template <int MODE>
__device__ __forceinline__ void moe_gemm_body(float* smf,
                                              const float* __restrict__ w,
                                              const float* __restrict__ bias,
                                              float* __restrict__ y) {
    unsigned int sbase = (unsigned int)__cvta_generic_to_shared(smf);

    int e = blockIdx.z;
    int n_e = min(g_cand_count[e], CAP);
    int row0 = blockIdx.x * BM;
    if (row0 >= n_e) return;

    int col0, kbeg;
    if (MODE == 1) {
        col0 = blockIdx.y * BN;
        kbeg = 0;
    } else {
        col0 = (blockIdx.y & 7) * BN;          // C_DIM/BN = 8 column tiles
        kbeg = (blockIdx.y >> 3) * KHALF;      // split 0 or 1
    }

    int tid = threadIdx.x, lane = tid & 31, wid = tid >> 5;
    int wm = wid >> 2, wn = wid & 3;   // warp tile 64(M) x 32(N)

    const int K   = (MODE == 1) ? C_DIM : KHALF;   // K length for THIS block
    const int LDB = (MODE == 1) ? H_DIM : C_DIM;
    const int NK  = K / BK;

    // ---- A fill: thread t -> rows t>>3 (+32,+64,+96), chunk t&7
    int aRow = tid >> 3;      // 0..31
    int aC   = tid & 7;
    const float* aSrc[4];
    unsigned int aDst[4];
#pragma unroll
    for (int i = 0; i < 4; i++) {
        int r = aRow + 32 * i;
        if (MODE == 1) {
            aSrc[i] = g_xt + (size_t)g_tb[e * CAP + row0 + r] * C_DIM;
        } else {
            aSrc[i] = g_h + ((size_t)e * CAP + row0 + r) * H_DIM + kbeg;
        }
        aDst[i] = (unsigned int)(r * 128 + (((aC + (r & 7)) & 7) << 4));
    }

    // ---- B fill: thread t -> row t>>3 (0..31), chunks (t&7)+8i, i=0..3
    int bRow = tid >> 3;      // 0..31 (k)
    int bC   = tid & 7;
    const float* bSrcBase = w + (size_t)e * C_DIM * H_DIM + (size_t)kbeg * LDB;
    unsigned int bDst[4];
#pragma unroll
    for (int i = 0; i < 4; i++) {
        int c = bC + 8 * i;   // chunk 0..31 in the 128-word row
        bDst[i] = (unsigned int)(32768 + bRow * 512 + (((4 * c + 8 * (bRow & 3)) & 127) << 2));
    }

    float acc[4][4][4];
#pragma unroll
    for (int a = 0; a < 4; a++)
#pragma unroll
        for (int b = 0; b < 4; b++)
#pragma unroll
            for (int c = 0; c < 4; c++) acc[a][b][c] = 0.f;

    // prologue: stage 0 (k0 = 0)
    {
#pragma unroll
        for (int i = 0; i < 4; i++)
            cpa16(sbase + aDst[i], aSrc[i] + aC * 4);
        const float* bRow0 = bSrcBase + (size_t)bRow * LDB + col0;
#pragma unroll
        for (int i = 0; i < 4; i++)
            cpa16(sbase + bDst[i], bRow0 + (bC + 8 * i) * 4);
        cpa_commit();
    }

    int l4 = lane >> 2;      // 0..7
    int l3 = lane & 3;       // 0..3

    for (int kc0 = 0; kc0 < NK; kc0++) {
        if (kc0 + 1 < NK) {
            int st = (kc0 + 1) & 1;
            int k0 = (kc0 + 1) * BK;
            unsigned int aofs = st ? 16384u : 0u;
            unsigned int bofs = st ? 16384u : 0u;
#pragma unroll
            for (int i = 0; i < 4; i++)
                cpa16(sbase + aDst[i] + aofs, aSrc[i] + k0 + aC * 4);
            const float* bRowK = bSrcBase + (size_t)(k0 + bRow) * LDB + col0;
#pragma unroll
            for (int i = 0; i < 4; i++)
                cpa16(sbase + bDst[i] + bofs, bRowK + (bC + 8 * i) * 4);
            cpa_commit();
            cpa_wait1();
        } else {
            cpa_wait0();
        }
        __syncthreads();

        int st = kc0 & 1;
        const float* As = smf + (st ? FA1 : FA0);
        const float* Bs = smf + (st ? FB1 : FB0);

#pragma unroll
        for (int kk = 0; kk < BK; kk += 8) {
            int kc = kk + l3;
            int c0w = (kc + 4 * l4) & 31;
            int c1w = (kc + 4 + 4 * l4) & 31;
            unsigned int af[4][4];
#pragma unroll
            for (int mt = 0; mt < 4; mt++) {
                int rb = wm * 64 + mt * 16 + l4;
                af[mt][0] = __float_as_uint(As[rb * 32 + c0w]);
                af[mt][1] = __float_as_uint(As[(rb + 8) * 32 + c0w]);
                af[mt][2] = __float_as_uint(As[rb * 32 + c1w]);
                af[mt][3] = __float_as_uint(As[(rb + 8) * 32 + c1w]);
            }
            unsigned int bf[4][2];
#pragma unroll
            for (int nt = 0; nt < 4; nt++) {
                int nb = wn * 32 + nt * 8 + l4;
                int cw = (nb + 8 * l3) & 127;
                bf[nt][0] = to_tf32_u(Bs[(kk + l3) * 128 + cw]);
                bf[nt][1] = to_tf32_u(Bs[(kk + 4 + l3) * 128 + cw]);
            }
#pragma unroll
            for (int mt = 0; mt < 4; mt++)
#pragma unroll
                for (int nt = 0; nt < 4; nt++)
                    mma_tf32(acc[mt][nt], af[mt], bf[nt]);
        }
        __syncthreads();
    }

    // ---------------- epilogue ----------------
    const float* brw = bias + (MODE == 1 ? e * H_DIM : e * C_DIM);
    const bool addBias = (MODE == 1) || (kbeg == 0);
#pragma unroll
    for (int mt = 0; mt < 4; mt++) {
#pragma unroll
        for (int half = 0; half < 2; half++) {
            int r = row0 + wm * 64 + mt * 16 + l4 + half * 8;
#pragma unroll
            for (int nt = 0; nt < 4; nt++) {
                int n0 = col0 + wn * 32 + nt * 8 + l3 * 2;
                float c0 = acc[mt][nt][half * 2 + 0];
                float c1 = acc[mt][nt][half * 2 + 1];
                if (MODE == 1) {
                    float v0 = to_tf32_f(gelu_exact(c0 + brw[n0]));
                    float v1 = to_tf32_f(gelu_exact(c1 + brw[n0 + 1]));
                    float2* hp = (float2*)(g_h + ((size_t)e * CAP + r) * H_DIM + n0);
                    *hp = make_float2(v0, v1);
                } else {
                    float gate = g_gb[e * CAP + r];
                    if (gate != 0.f) {
                        int tok = g_tb[e * CAP + r];
                        float b0 = addBias ? brw[n0] : 0.f;
                        float b1 = addBias ? brw[n0 + 1] : 0.f;
                        float* yrow = y + (size_t)tok * C_DIM + n0;
                        atomicAdd(&yrow[0], (c0 + b0) * gate);
                        atomicAdd(&yrow[1], (c1 + b1) * gate);
                    }
                }
            }
        }
    }
}

// concrete kernels: cap regs at 128 (2 blocks/SM)
__global__ void __launch_bounds__(256, 2) moe_gemm1(const float* __restrict__ w1,
                                                    const float* __restrict__ b1) {
    extern __shared__ float smf_g1[];
    moe_gemm_body<1>(smf_g1, w1, b1, (float*)0);
}
__global__ void __launch_bounds__(256, 2) moe_gemm2(const float* __restrict__ w2,
                                                    const float* __restrict__ b2,
                                                    float* __restrict__ y) {
    extern __shared__ float smf_g2[];
    moe_gemm_body<2>(smf_g2, w2, b2, y);
}

// ---------------- aux loss ----------------
__global__ void aux_kernel(float* __restrict__ out, int out_size) {
    if (out_size <= S_TOK * C_DIM) return;
    float total = 0.f;
    float kept[NEXP];
    for (int e = 0; e < NEXP; e++) {
        kept[e] = (float)min(g_cand_count[e], CAP);
        total += kept[e];
    }
    float aux = 0.f;
    for (int e = 0; e < NEXP; e++) {
        float pm = g_probs_sum[e] / (float)S_TOK;
        aux += pm * (kept[e] / (total + 1e-9f));
    }
    out[S_TOK * C_DIM] = aux * (float)NEXP;
}

// ---------------- launch ----------------
extern "C" void kernel_launch(void* const* d_in, const int* in_sizes, int n_in,
                              void* d_out, int out_size) {
    const float* x  = (const float*)d_in[0];
    const float* rw = (const float*)d_in[1];
    const float* rb = (const float*)d_in[2];
    const float* w1 = (const float*)d_in[3];
    const float* b1 = (const float*)d_in[4];
    const float* w2 = (const float*)d_in[5];
    const float* b2 = (const float*)d_in[6];
    float* out = (float*)d_out;

    cudaFuncSetAttribute((const void*)moe_gemm1,
                         cudaFuncAttributeMaxDynamicSharedMemorySize, SMEM_GEMM_BYTES);
    cudaFuncSetAttribute((const void*)moe_gemm2,
                         cudaFuncAttributeMaxDynamicSharedMemorySize, SMEM_GEMM_BYTES);

    init_kernel<<<(NEXP * CAP + 255) / 256, 256>>>();
    cudaMemsetAsync(d_out, 0, (size_t)out_size * sizeof(float));

    convert_x_kernel<<<(S_TOK * C_DIM + 255) / 256, 256>>>(x);
    router_kernel<<<S_TOK / 8, 256>>>(x, rw, rb);
    rank_kernel<<<dim3(S_TOK / 256, NEXP), 256>>>();

    moe_gemm1<<<dim3(CAP / BM, H_DIM / BN, NEXP), 256, SMEM_GEMM_BYTES>>>(w1, b1);
    // GEMM2: split-K=2 -> gridDim.y = 8 column tiles * 2 splits
    moe_gemm2<<<dim3(CAP / BM, (C_DIM / BN) * KSPLIT2, NEXP), 256, SMEM_GEMM_BYTES>>>(w2, b2, out);

    aux_kernel<<<1, 1>>>(out, out_size);
}